// round 12
// baseline (speedup 1.0000x reference)
#include <cuda_runtime.h>
#include <cuda_fp16.h>
#include <cstdint>

#define B_   32
#define T_   1024
#define C_   128
#define EPS_ 1e-5f
#define SCL  0.08838834764831845f          // 1/sqrt(128)
#define K2E  0.1275187502506137f           // SCL * log2(e)

// Scratch (deterministic: valid slots rewritten identically each launch;
// zero-initialized padded slots never written).
__device__ float g_padded[B_ * T_ * C_];   // 16 MB

// ---------------------------------------------------------------------------
__device__ __forceinline__ float f2tf(float x) {
    uint32_t u;
    asm("cvt.rna.tf32.f32 %0, %1;" : "=r"(u) : "f"(x));
    return __uint_as_float(u);
}
__device__ __forceinline__ float ex2(float x) {
    float r;
    asm("ex2.approx.f32 %0, %1;" : "=f"(r) : "f"(x));
    return r;
}
__device__ __forceinline__ uint32_t h2pack(float a, float b) {
    __half2 h = __floats2half2_rn(a, b);
    return *(uint32_t*)&h;
}
__device__ __forceinline__ void mma_tf32(float* c, const float* a, const float* b) {
    const uint32_t* A = reinterpret_cast<const uint32_t*>(a);
    const uint32_t* Bp = reinterpret_cast<const uint32_t*>(b);
    asm volatile(
        "mma.sync.aligned.m16n8k8.row.col.f32.tf32.tf32.f32 "
        "{%0,%1,%2,%3}, {%4,%5,%6,%7}, {%8,%9}, {%0,%1,%2,%3};\n"
        : "+f"(c[0]), "+f"(c[1]), "+f"(c[2]), "+f"(c[3])
        : "r"(A[0]), "r"(A[1]), "r"(A[2]), "r"(A[3]), "r"(Bp[0]), "r"(Bp[1]));
}
__device__ __forceinline__ void mma_f16(float* c, const uint32_t* a, const uint32_t* b) {
    asm volatile(
        "mma.sync.aligned.m16n8k16.row.col.f32.f16.f16.f32 "
        "{%0,%1,%2,%3}, {%4,%5,%6,%7}, {%8,%9}, {%0,%1,%2,%3};\n"
        : "+f"(c[0]), "+f"(c[1]), "+f"(c[2]), "+f"(c[3])
        : "r"(a[0]), "r"(a[1]), "r"(a[2]), "r"(a[3]), "r"(b[0]), "r"(b[1]));
}

// ---------------------------------------------------------------------------
// K1 (tf32 MMA): h = leaky(BN(concat(x_temp, x_stat[bidx]) @ W1^T + b1))
// Last block (blockIdx.x == gridDim.x-1) instead computes the stat branch.
// ---------------------------------------------------------------------------
#define K1_SMEM_FLOATS (64 * 68 + 128 * 68)

__global__ void __launch_bounds__(256, 2)
k1_mma(const float* __restrict__ x_temp, const float* __restrict__ x_stat,
       const int* __restrict__ bidx, const int* __restrict__ pidx,
       const float* __restrict__ W1, const float* __restrict__ b1,
       const float* __restrict__ g1, const float* __restrict__ be1,
       const float* __restrict__ mu1, const float* __restrict__ v1,
       const float* __restrict__ W2, const float* __restrict__ b2,
       const float* __restrict__ g2, const float* __restrict__ be2,
       const float* __restrict__ mu2, const float* __restrict__ v2,
       float* __restrict__ stat_out, int N) {
    extern __shared__ float sm[];

    // ---- stat branch block (tiny: 32x64 GEMM + BN + leaky) ----
    if (blockIdx.x == gridDim.x - 1) {
        const int tid = threadIdx.x;
        int c = tid & 63;
        int b0r = tid >> 6;            // 0..3
        float s = g2[c] * rsqrtf(v2[c] + EPS_);
        float o = (b2[c] - mu2[c]) * s + be2[c];
#pragma unroll
        for (int bb = 0; bb < 8; bb++) {
            int b = b0r * 8 + bb;
            float a = 0.f;
#pragma unroll 8
            for (int k = 0; k < 64; k++) a += x_stat[b * 64 + k] * W2[c * 64 + k];
            float h = a * s + o;
            stat_out[b * 64 + c] = (h >= 0.f) ? h : 0.01f * h;
        }
        return;
    }

    float* Xs = sm;              // [64][68]
    float* Ws = sm + 64 * 68;    // [128][68]

    const int n0  = blockIdx.x * 64;
    const int tid = threadIdx.x;
    const int wid = tid >> 5, lane = tid & 31;
    const int wm  = wid >> 1, wn = wid & 1;
    const int g   = lane >> 2, tg = lane & 3;
    const int qr  = wm * 16 + g;

    float acc[8][4];
#pragma unroll
    for (int ch = 0; ch < 8; ch++)
#pragma unroll
        for (int i = 0; i < 4; i++) acc[ch][i] = 0.f;

    for (int ck = 0; ck < 3; ck++) {
        __syncthreads();
#pragma unroll
        for (int it = 0; it < 4; it++) {
            int e = (tid + it * 256) * 4;
            int r = e >> 6, k4 = e & 63;
            int n = n0 + r;
            float4 v = make_float4(0.f, 0.f, 0.f, 0.f);
            if (n < N) {
                if (ck < 2)
                    v = *(const float4*)&x_temp[(size_t)n * 128 + ck * 64 + k4];
                else
                    v = *(const float4*)&x_stat[bidx[n] * 64 + k4];
            }
            *(float4*)&Xs[r * 68 + k4] =
                make_float4(f2tf(v.x), f2tf(v.y), f2tf(v.z), f2tf(v.w));
        }
#pragma unroll
        for (int it = 0; it < 8; it++) {
            int e = (tid + it * 256) * 4;
            int c = e >> 6, k4 = e & 63;
            float4 v = *(const float4*)&W1[(size_t)c * 192 + ck * 64 + k4];
            *(float4*)&Ws[c * 68 + k4] =
                make_float4(f2tf(v.x), f2tf(v.y), f2tf(v.z), f2tf(v.w));
        }
        __syncthreads();

#pragma unroll
        for (int kk = 0; kk < 8; kk++) {
            int kb = kk * 8 + tg;
            float af[4];
            af[0] = Xs[qr * 68 + kb];
            af[1] = Xs[(qr + 8) * 68 + kb];
            af[2] = Xs[qr * 68 + kb + 4];
            af[3] = Xs[(qr + 8) * 68 + kb + 4];
#pragma unroll
            for (int ch = 0; ch < 8; ch++) {
                int nc = wn * 64 + ch * 8 + g;
                float bb[2] = { Ws[nc * 68 + kb], Ws[nc * 68 + kb + 4] };
                mma_tf32(acc[ch], af, bb);
            }
        }
    }

    int nA = n0 + qr, nB = n0 + qr + 8;
    int bbA = 0, ttA = 0, bbB = 0, ttB = 0;
    if (nA < N) { bbA = bidx[nA]; ttA = pidx[nA]; }
    if (nB < N) { bbB = bidx[nB]; ttB = pidx[nB]; }
#pragma unroll
    for (int ch = 0; ch < 8; ch++) {
        int c = wn * 64 + ch * 8 + 2 * tg;
        float s0 = g1[c]     * rsqrtf(v1[c]     + EPS_);
        float s1 = g1[c + 1] * rsqrtf(v1[c + 1] + EPS_);
        float o0 = (b1[c]     - mu1[c])     * s0 + be1[c];
        float o1 = (b1[c + 1] - mu1[c + 1]) * s1 + be1[c + 1];
        if (nA < N) {
            float h0 = acc[ch][0] * s0 + o0;
            float h1 = acc[ch][1] * s1 + o1;
            h0 = (h0 >= 0.f) ? h0 : 0.01f * h0;
            h1 = (h1 >= 0.f) ? h1 : 0.01f * h1;
            *(float2*)&g_padded[((size_t)bbA * T_ + ttA) * C_ + c] = make_float2(h0, h1);
        }
        if (nB < N) {
            float h2 = acc[ch][2] * s0 + o0;
            float h3 = acc[ch][3] * s1 + o1;
            h2 = (h2 >= 0.f) ? h2 : 0.01f * h2;
            h3 = (h3 >= 0.f) ? h3 : 0.01f * h3;
            *(float2*)&g_padded[((size_t)bbB * T_ + ttB) * C_ + c] = make_float2(h2, h3);
        }
    }
}

// ---------------------------------------------------------------------------
// Fused attention, fp16 m16n8k16 MMA (fp32 accum):
//   per key tile: S = QK^T, E = exp(S*SCL) (no max-sub: logits bounded),
//   d += rowsum(E), accS += E@V, accT += temp@V;  out = accS/(d+pad) + accT
// smem (b32 units):
//   Qh [64][68]  row-major half2   (QK A-frags CF: bank 4g+tg)
//   Kh [64][68]  row-major half2   (QK B-frags CF)
//   Vp [32][136] key-paired half2: Vp[k2][ch] = (V[2k2][ch], V[2k2+1][ch])
//                                  (PV B-frags = 1 LDS.32, CF: bank 8tg+g)
//   Ph/Th [64][36] half2           (PV A-frags CF)
// ---------------------------------------------------------------------------
#define QH_P 68
#define KH_P 68
#define VP_P 136
#define PH_P 36
#define AT_SMEM_U32 (64*QH_P + 64*KH_P + 32*VP_P + 64*PH_P + 64*PH_P + 64 + 128)

__global__ void __launch_bounds__(256, 2)
attn_fused(const int* __restrict__ lengths,
           const float* __restrict__ temp_attn,
           float* __restrict__ out) {
    extern __shared__ uint32_t smu[];
    uint32_t* Qh = smu;                      // [64][68]
    uint32_t* Kh = Qh + 64 * QH_P;           // [64][68]
    uint32_t* Vp = Kh + 64 * KH_P;           // [32][136]
    uint32_t* Ph = Vp + 32 * VP_P;           // [64][36]
    uint32_t* Th = Ph + 64 * PH_P;           // [64][36]
    float*   dacc = (float*)(Th + 64 * PH_P);  // [64]
    float*   psum = dacc + 64;                 // [2][64]
    float*   inv  = psum;                      // reused in epilogue

    const int b = blockIdx.y;
    const int len = lengths[b];
    const int tile0 = blockIdx.x * 64;
    if (tile0 >= len) return;

    const int tid  = threadIdx.x;
    const int wid  = tid >> 5, lane = tid & 31;
    const int wm   = wid >> 1, wn = wid & 1;
    const int g    = lane >> 2, tg = lane & 3;
    const int qr   = wm * 16 + g;
    const float* pb = g_padded + (size_t)b * T_ * C_;

    int ro = 0;
    for (int i = 0; i < b; i++) ro += lengths[i];

    if (tid < 64) dacc[tid] = 0.f;

    // Q tile: row pairs -> half2 rows
#pragma unroll
    for (int it = 0; it < 4; it++) {
        int idx = tid + it * 256;            // 0..1023
        int r2 = idx >> 5, cb = (idx & 31) * 4;
        float4 v0 = *(const float4*)&pb[(size_t)(tile0 + 2 * r2)     * C_ + cb];
        float4 v1 = *(const float4*)&pb[(size_t)(tile0 + 2 * r2 + 1) * C_ + cb];
        *(uint2*)&Qh[(2 * r2)     * QH_P + cb / 2] =
            make_uint2(h2pack(v0.x, v0.y), h2pack(v0.z, v0.w));
        *(uint2*)&Qh[(2 * r2 + 1) * QH_P + cb / 2] =
            make_uint2(h2pack(v1.x, v1.y), h2pack(v1.z, v1.w));
    }

    float accS[8][4], accT[8][4];
#pragma unroll
    for (int ch = 0; ch < 8; ch++)
#pragma unroll
        for (int i = 0; i < 4; i++) { accS[ch][i] = 0.f; accT[ch][i] = 0.f; }

    const float* tb = temp_attn + ((size_t)b * T_ + tile0) * T_;
    const int nkt = (len + 63) >> 6;

    for (int kt = 0; kt < nkt; kt++) {
        __syncthreads();
        // K/V tile: read row pairs; Kh row-major + Vp key-paired transpose
#pragma unroll
        for (int it = 0; it < 4; it++) {
            int idx = tid + it * 256;
            int r2 = idx >> 5, cb = (idx & 31) * 4;
            const float* src = &pb[(size_t)(kt * 64 + 2 * r2) * C_ + cb];
            float4 v0 = *(const float4*)src;
            float4 v1 = *(const float4*)(src + C_);
            *(uint2*)&Kh[(2 * r2)     * KH_P + cb / 2] =
                make_uint2(h2pack(v0.x, v0.y), h2pack(v0.z, v0.w));
            *(uint2*)&Kh[(2 * r2 + 1) * KH_P + cb / 2] =
                make_uint2(h2pack(v1.x, v1.y), h2pack(v1.z, v1.w));
            Vp[r2 * VP_P + cb]     = h2pack(v0.x, v1.x);
            Vp[r2 * VP_P + cb + 1] = h2pack(v0.y, v1.y);
            Vp[r2 * VP_P + cb + 2] = h2pack(v0.z, v1.z);
            Vp[r2 * VP_P + cb + 3] = h2pack(v0.w, v1.w);
        }
        // temp tile -> half2
#pragma unroll
        for (int it = 0; it < 4; it++) {
            int e = (tid + it * 256) * 4;
            int r = e >> 6, c = e & 63;
            float4 v = *(const float4*)&tb[(size_t)r * T_ + kt * 64 + c];
            *(uint2*)&Th[r * PH_P + c / 2] =
                make_uint2(h2pack(v.x, v.y), h2pack(v.z, v.w));
        }
        __syncthreads();

        // S = Q K^T (warp: 16 rows x 32 keys), fp16 k16
        float c4[4][4];
#pragma unroll
        for (int ch = 0; ch < 4; ch++)
#pragma unroll
            for (int i = 0; i < 4; i++) c4[ch][i] = 0.f;
#pragma unroll
        for (int kk = 0; kk < 8; kk++) {
            int kb = kk * 8 + tg;
            uint32_t af[4];
            af[0] = Qh[qr * QH_P + kb];
            af[1] = Qh[(qr + 8) * QH_P + kb];
            af[2] = Qh[qr * QH_P + kb + 4];
            af[3] = Qh[(qr + 8) * QH_P + kb + 4];
#pragma unroll
            for (int ch = 0; ch < 4; ch++) {
                int nc = wn * 32 + ch * 8 + g;
                uint32_t bf[2] = { Kh[nc * KH_P + kb], Kh[nc * KH_P + kb + 4] };
                mma_f16(c4[ch], af, bf);
            }
        }

        // E = exp(S*SCL); stage to Ph (half2: two adjacent cols per lane)
        float eA = 0.f, eB = 0.f;
#pragma unroll
        for (int ch = 0; ch < 4; ch++) {
            float e0 = fminf(ex2(c4[ch][0] * K2E), 60000.f);
            float e1 = fminf(ex2(c4[ch][1] * K2E), 60000.f);
            float e2 = fminf(ex2(c4[ch][2] * K2E), 60000.f);
            float e3 = fminf(ex2(c4[ch][3] * K2E), 60000.f);
            eA += e0 + e1;
            eB += e2 + e3;
            int cc = wn * 16 + ch * 4 + tg;
            Ph[qr * PH_P + cc]       = h2pack(e0, e1);
            Ph[(qr + 8) * PH_P + cc] = h2pack(e2, e3);
        }
#pragma unroll
        for (int off = 1; off <= 2; off <<= 1) {
            eA += __shfl_xor_sync(0xffffffffu, eA, off);
            eB += __shfl_xor_sync(0xffffffffu, eB, off);
        }
        if (tg == 0) { psum[wn * 64 + qr] = eA; psum[wn * 64 + qr + 8] = eB; }
        __syncthreads();

        // accS += E @ V ; accT += temp @ V (fp16 k16, shared B-frags)
#pragma unroll
        for (int kk = 0; kk < 4; kk++) {
            int kb = kk * 8 + tg;
            uint32_t aE[4], aT[4];
            aE[0] = Ph[qr * PH_P + kb];
            aE[1] = Ph[(qr + 8) * PH_P + kb];
            aE[2] = Ph[qr * PH_P + kb + 4];
            aE[3] = Ph[(qr + 8) * PH_P + kb + 4];
            aT[0] = Th[qr * PH_P + kb];
            aT[1] = Th[(qr + 8) * PH_P + kb];
            aT[2] = Th[qr * PH_P + kb + 4];
            aT[3] = Th[(qr + 8) * PH_P + kb + 4];
#pragma unroll
            for (int ch = 0; ch < 8; ch++) {
                int nc = wn * 64 + ch * 8 + g;
                uint32_t bf[2] = { Vp[(kk * 8 + tg) * VP_P + nc],
                                   Vp[(kk * 8 + tg + 4) * VP_P + nc] };
                mma_f16(accS[ch], aE, bf);
                mma_f16(accT[ch], aT, bf);
            }
        }
        if (tid < 64) dacc[tid] += psum[tid] + psum[64 + tid];
    }

    __syncthreads();
    if (tid < 64) {
        float d = dacc[tid] + (float)(T_ - nkt * 64);   // pad cols: exp(0)=1 each
        inv[tid] = 1.f / d;
    }
    __syncthreads();

    const float iA = inv[qr], iB = inv[qr + 8];
    const int tA = tile0 + qr, tB = tA + 8;
#pragma unroll
    for (int ch = 0; ch < 8; ch++) {
        int cc = wn * 64 + ch * 8 + 2 * tg;
        if (tA < len)
            *(float2*)&out[(size_t)(ro + tA) * C_ + cc] =
                make_float2(accS[ch][0] * iA + accT[ch][0],
                            accS[ch][1] * iA + accT[ch][1]);
        if (tB < len)
            *(float2*)&out[(size_t)(ro + tB) * C_ + cc] =
                make_float2(accS[ch][2] * iB + accT[ch][2],
                            accS[ch][3] * iB + accT[ch][3]);
    }
}

// ---------------------------------------------------------------------------
extern "C" void kernel_launch(void* const* d_in, const int* in_sizes, int n_in,
                              void* d_out, int out_size) {
    const float* x_temp    = (const float*)d_in[0];
    const float* x_stat    = (const float*)d_in[1];
    const float* temp_attn = (const float*)d_in[2];
    // d_in[3] = mask_repeat (unused; implicit from lengths)
    const int*   lengths   = (const int*)d_in[4];
    const int*   batch_idx = (const int*)d_in[5];
    const int*   pos_idx   = (const int*)d_in[6];
    const float* W1 = (const float*)d_in[7];
    const float* b1 = (const float*)d_in[8];
    const float* g1 = (const float*)d_in[9];
    const float* be1= (const float*)d_in[10];
    const float* mu1= (const float*)d_in[11];
    const float* v1 = (const float*)d_in[12];
    const float* W2 = (const float*)d_in[13];
    const float* b2 = (const float*)d_in[14];
    const float* g2 = (const float*)d_in[15];
    const float* be2= (const float*)d_in[16];
    const float* mu2= (const float*)d_in[17];
    const float* v2 = (const float*)d_in[18];

    const int N = in_sizes[0] / 128;
    float* out = (float*)d_out;

    cudaFuncSetAttribute(k1_mma, cudaFuncAttributeMaxDynamicSharedMemorySize,
                         K1_SMEM_FLOATS * 4);
    cudaFuncSetAttribute(attn_fused, cudaFuncAttributeMaxDynamicSharedMemorySize,
                         AT_SMEM_U32 * 4);

    int nblk = (N + 63) / 64;
    k1_mma<<<nblk + 1, 256, K1_SMEM_FLOATS * 4>>>(x_temp, x_stat, batch_idx, pos_idx,
                                                  W1, b1, g1, be1, mu1, v1,
                                                  W2, b2, g2, be2, mu2, v2,
                                                  out + (size_t)N * C_, N);
    dim3 grid(T_ / 64, B_);
    attn_fused<<<grid, 256, AT_SMEM_U32 * 4>>>(lengths, temp_attn, out);
}

// round 14
// speedup vs baseline: 1.0252x; 1.0252x over previous
#include <cuda_runtime.h>
#include <cuda_fp16.h>
#include <cstdint>

#define B_   32
#define T_   1024
#define C_   128
#define EPS_ 1e-5f
#define SCL  0.08838834764831845f          // 1/sqrt(128)
#define K2E  0.1275187502506137f           // SCL * log2(e)

// Scratch (deterministic: valid slots rewritten identically each launch;
// zero-initialized padded slots never written).
__device__ float g_padded[B_ * T_ * C_];   // 16 MB

// ---------------------------------------------------------------------------
__device__ __forceinline__ float f2tf(float x) {
    uint32_t u;
    asm("cvt.rna.tf32.f32 %0, %1;" : "=r"(u) : "f"(x));
    return __uint_as_float(u);
}
__device__ __forceinline__ float ex2(float x) {
    float r;
    asm("ex2.approx.f32 %0, %1;" : "=f"(r) : "f"(x));
    return r;
}
__device__ __forceinline__ uint32_t h2pack(float a, float b) {
    __half2 h = __floats2half2_rn(a, b);
    return *(uint32_t*)&h;
}
__device__ __forceinline__ void mma_tf32(float* c, const float* a, const float* b) {
    const uint32_t* A = reinterpret_cast<const uint32_t*>(a);
    const uint32_t* Bp = reinterpret_cast<const uint32_t*>(b);
    asm volatile(
        "mma.sync.aligned.m16n8k8.row.col.f32.tf32.tf32.f32 "
        "{%0,%1,%2,%3}, {%4,%5,%6,%7}, {%8,%9}, {%0,%1,%2,%3};\n"
        : "+f"(c[0]), "+f"(c[1]), "+f"(c[2]), "+f"(c[3])
        : "r"(A[0]), "r"(A[1]), "r"(A[2]), "r"(A[3]), "r"(Bp[0]), "r"(Bp[1]));
}
__device__ __forceinline__ void mma_f16(float* c, const uint32_t* a, const uint32_t* b) {
    asm volatile(
        "mma.sync.aligned.m16n8k16.row.col.f32.f16.f16.f32 "
        "{%0,%1,%2,%3}, {%4,%5,%6,%7}, {%8,%9}, {%0,%1,%2,%3};\n"
        : "+f"(c[0]), "+f"(c[1]), "+f"(c[2]), "+f"(c[3])
        : "r"(a[0]), "r"(a[1]), "r"(a[2]), "r"(a[3]), "r"(b[0]), "r"(b[1]));
}

// ---------------------------------------------------------------------------
// K1 (tf32 MMA): h = leaky(BN(concat(x_temp, x_stat[bidx]) @ W1^T + b1))
// Last block (blockIdx.x == gridDim.x-1) instead computes the stat branch.
// ---------------------------------------------------------------------------
#define K1_SMEM_FLOATS (64 * 68 + 128 * 68)

__global__ void __launch_bounds__(256, 2)
k1_mma(const float* __restrict__ x_temp, const float* __restrict__ x_stat,
       const int* __restrict__ bidx, const int* __restrict__ pidx,
       const float* __restrict__ W1, const float* __restrict__ b1,
       const float* __restrict__ g1, const float* __restrict__ be1,
       const float* __restrict__ mu1, const float* __restrict__ v1,
       const float* __restrict__ W2, const float* __restrict__ b2,
       const float* __restrict__ g2, const float* __restrict__ be2,
       const float* __restrict__ mu2, const float* __restrict__ v2,
       float* __restrict__ stat_out, int N) {
    extern __shared__ float sm[];

    // ---- stat branch block (tiny: 32x64 GEMM + BN + leaky) ----
    if (blockIdx.x == gridDim.x - 1) {
        const int tid = threadIdx.x;
        int c = tid & 63;
        int b0r = tid >> 6;            // 0..3
        float s = g2[c] * rsqrtf(v2[c] + EPS_);
        float o = (b2[c] - mu2[c]) * s + be2[c];
#pragma unroll
        for (int bb = 0; bb < 8; bb++) {
            int b = b0r * 8 + bb;
            float a = 0.f;
#pragma unroll 8
            for (int k = 0; k < 64; k++) a += x_stat[b * 64 + k] * W2[c * 64 + k];
            float h = a * s + o;
            stat_out[b * 64 + c] = (h >= 0.f) ? h : 0.01f * h;
        }
        return;
    }

    float* Xs = sm;              // [64][68]
    float* Ws = sm + 64 * 68;    // [128][68]

    const int n0  = blockIdx.x * 64;
    const int tid = threadIdx.x;
    const int wid = tid >> 5, lane = tid & 31;
    const int wm  = wid >> 1, wn = wid & 1;
    const int g   = lane >> 2, tg = lane & 3;
    const int qr  = wm * 16 + g;

    float acc[8][4];
#pragma unroll
    for (int ch = 0; ch < 8; ch++)
#pragma unroll
        for (int i = 0; i < 4; i++) acc[ch][i] = 0.f;

    for (int ck = 0; ck < 3; ck++) {
        __syncthreads();
#pragma unroll
        for (int it = 0; it < 4; it++) {
            int e = (tid + it * 256) * 4;
            int r = e >> 6, k4 = e & 63;
            int n = n0 + r;
            float4 v = make_float4(0.f, 0.f, 0.f, 0.f);
            if (n < N) {
                if (ck < 2)
                    v = *(const float4*)&x_temp[(size_t)n * 128 + ck * 64 + k4];
                else
                    v = *(const float4*)&x_stat[bidx[n] * 64 + k4];
            }
            *(float4*)&Xs[r * 68 + k4] =
                make_float4(f2tf(v.x), f2tf(v.y), f2tf(v.z), f2tf(v.w));
        }
#pragma unroll
        for (int it = 0; it < 8; it++) {
            int e = (tid + it * 256) * 4;
            int c = e >> 6, k4 = e & 63;
            float4 v = *(const float4*)&W1[(size_t)c * 192 + ck * 64 + k4];
            *(float4*)&Ws[c * 68 + k4] =
                make_float4(f2tf(v.x), f2tf(v.y), f2tf(v.z), f2tf(v.w));
        }
        __syncthreads();

#pragma unroll
        for (int kk = 0; kk < 8; kk++) {
            int kb = kk * 8 + tg;
            float af[4];
            af[0] = Xs[qr * 68 + kb];
            af[1] = Xs[(qr + 8) * 68 + kb];
            af[2] = Xs[qr * 68 + kb + 4];
            af[3] = Xs[(qr + 8) * 68 + kb + 4];
#pragma unroll
            for (int ch = 0; ch < 8; ch++) {
                int nc = wn * 64 + ch * 8 + g;
                float bb[2] = { Ws[nc * 68 + kb], Ws[nc * 68 + kb + 4] };
                mma_tf32(acc[ch], af, bb);
            }
        }
    }

    int nA = n0 + qr, nB = n0 + qr + 8;
    int bbA = 0, ttA = 0, bbB = 0, ttB = 0;
    if (nA < N) { bbA = bidx[nA]; ttA = pidx[nA]; }
    if (nB < N) { bbB = bidx[nB]; ttB = pidx[nB]; }
#pragma unroll
    for (int ch = 0; ch < 8; ch++) {
        int c = wn * 64 + ch * 8 + 2 * tg;
        float s0 = g1[c]     * rsqrtf(v1[c]     + EPS_);
        float s1 = g1[c + 1] * rsqrtf(v1[c + 1] + EPS_);
        float o0 = (b1[c]     - mu1[c])     * s0 + be1[c];
        float o1 = (b1[c + 1] - mu1[c + 1]) * s1 + be1[c + 1];
        if (nA < N) {
            float h0 = acc[ch][0] * s0 + o0;
            float h1 = acc[ch][1] * s1 + o1;
            h0 = (h0 >= 0.f) ? h0 : 0.01f * h0;
            h1 = (h1 >= 0.f) ? h1 : 0.01f * h1;
            *(float2*)&g_padded[((size_t)bbA * T_ + ttA) * C_ + c] = make_float2(h0, h1);
        }
        if (nB < N) {
            float h2 = acc[ch][2] * s0 + o0;
            float h3 = acc[ch][3] * s1 + o1;
            h2 = (h2 >= 0.f) ? h2 : 0.01f * h2;
            h3 = (h3 >= 0.f) ? h3 : 0.01f * h3;
            *(float2*)&g_padded[((size_t)bbB * T_ + ttB) * C_ + c] = make_float2(h2, h3);
        }
    }
}

// ---------------------------------------------------------------------------
// Fused attention, fp16 m16n8k16 MMA (fp32 accum):
//   per key tile: S = QK^T, E = exp(S*SCL) (no max-sub: logits bounded),
//   d += rowsum(E), accS += E@V, accT += temp@V;  out = accS/(d+pad) + accT
// smem (b32 units):
//   Qh [64][68]  row-major half2   (QK A-frags CF: bank 4g+tg)
//   Kh [64][68]  row-major half2   (QK B-frags CF)
//   Vp [32][136] key-paired half2: Vp[k2][ch] = (V[2k2][ch], V[2k2+1][ch])
//                                  (PV B-frags = 1 LDS.32, CF: bank 8tg+g)
//   Ph/Th [64][36] half2           (PV A-frags CF)
// ---------------------------------------------------------------------------
#define QH_P 68
#define KH_P 68
#define VP_P 136
#define PH_P 36
#define AT_SMEM_U32 (64*QH_P + 64*KH_P + 32*VP_P + 64*PH_P + 64*PH_P + 64 + 128)

__global__ void __launch_bounds__(256, 2)
attn_fused(const int* __restrict__ lengths,
           const float* __restrict__ temp_attn,
           float* __restrict__ out) {
    extern __shared__ uint32_t smu[];
    uint32_t* Qh = smu;                      // [64][68]
    uint32_t* Kh = Qh + 64 * QH_P;           // [64][68]
    uint32_t* Vp = Kh + 64 * KH_P;           // [32][136]
    uint32_t* Ph = Vp + 32 * VP_P;           // [64][36]
    uint32_t* Th = Ph + 64 * PH_P;           // [64][36]
    float*   dacc = (float*)(Th + 64 * PH_P);  // [64]
    float*   psum = dacc + 64;                 // [2][64]
    float*   inv  = psum;                      // reused in epilogue

    const int b = blockIdx.y;
    const int len = lengths[b];
    const int tile0 = blockIdx.x * 64;
    if (tile0 >= len) return;

    const int tid  = threadIdx.x;
    const int wid  = tid >> 5, lane = tid & 31;
    const int wm   = wid >> 1, wn = wid & 1;
    const int g    = lane >> 2, tg = lane & 3;
    const int qr   = wm * 16 + g;
    const float* pb = g_padded + (size_t)b * T_ * C_;

    int ro = 0;
    for (int i = 0; i < b; i++) ro += lengths[i];

    if (tid < 64) dacc[tid] = 0.f;

    // Q tile: row pairs -> half2 rows
#pragma unroll
    for (int it = 0; it < 4; it++) {
        int idx = tid + it * 256;            // 0..1023
        int r2 = idx >> 5, cb = (idx & 31) * 4;
        float4 v0 = *(const float4*)&pb[(size_t)(tile0 + 2 * r2)     * C_ + cb];
        float4 v1 = *(const float4*)&pb[(size_t)(tile0 + 2 * r2 + 1) * C_ + cb];
        *(uint2*)&Qh[(2 * r2)     * QH_P + cb / 2] =
            make_uint2(h2pack(v0.x, v0.y), h2pack(v0.z, v0.w));
        *(uint2*)&Qh[(2 * r2 + 1) * QH_P + cb / 2] =
            make_uint2(h2pack(v1.x, v1.y), h2pack(v1.z, v1.w));
    }

    float accS[8][4], accT[8][4];
#pragma unroll
    for (int ch = 0; ch < 8; ch++)
#pragma unroll
        for (int i = 0; i < 4; i++) { accS[ch][i] = 0.f; accT[ch][i] = 0.f; }

    const float* tb = temp_attn + ((size_t)b * T_ + tile0) * T_;
    const int nkt = (len + 63) >> 6;

    for (int kt = 0; kt < nkt; kt++) {
        __syncthreads();
        // K/V tile: read row pairs; Kh row-major + Vp key-paired transpose
#pragma unroll
        for (int it = 0; it < 4; it++) {
            int idx = tid + it * 256;
            int r2 = idx >> 5, cb = (idx & 31) * 4;
            const float* src = &pb[(size_t)(kt * 64 + 2 * r2) * C_ + cb];
            float4 v0 = *(const float4*)src;
            float4 v1 = *(const float4*)(src + C_);
            *(uint2*)&Kh[(2 * r2)     * KH_P + cb / 2] =
                make_uint2(h2pack(v0.x, v0.y), h2pack(v0.z, v0.w));
            *(uint2*)&Kh[(2 * r2 + 1) * KH_P + cb / 2] =
                make_uint2(h2pack(v1.x, v1.y), h2pack(v1.z, v1.w));
            Vp[r2 * VP_P + cb]     = h2pack(v0.x, v1.x);
            Vp[r2 * VP_P + cb + 1] = h2pack(v0.y, v1.y);
            Vp[r2 * VP_P + cb + 2] = h2pack(v0.z, v1.z);
            Vp[r2 * VP_P + cb + 3] = h2pack(v0.w, v1.w);
        }
        // temp tile -> half2
#pragma unroll
        for (int it = 0; it < 4; it++) {
            int e = (tid + it * 256) * 4;
            int r = e >> 6, c = e & 63;
            float4 v = *(const float4*)&tb[(size_t)r * T_ + kt * 64 + c];
            *(uint2*)&Th[r * PH_P + c / 2] =
                make_uint2(h2pack(v.x, v.y), h2pack(v.z, v.w));
        }
        __syncthreads();

        // S = Q K^T (warp: 16 rows x 32 keys), fp16 k16
        float c4[4][4];
#pragma unroll
        for (int ch = 0; ch < 4; ch++)
#pragma unroll
            for (int i = 0; i < 4; i++) c4[ch][i] = 0.f;
#pragma unroll
        for (int kk = 0; kk < 8; kk++) {
            int kb = kk * 8 + tg;
            uint32_t af[4];
            af[0] = Qh[qr * QH_P + kb];
            af[1] = Qh[(qr + 8) * QH_P + kb];
            af[2] = Qh[qr * QH_P + kb + 4];
            af[3] = Qh[(qr + 8) * QH_P + kb + 4];
#pragma unroll
            for (int ch = 0; ch < 4; ch++) {
                int nc = wn * 32 + ch * 8 + g;
                uint32_t bf[2] = { Kh[nc * KH_P + kb], Kh[nc * KH_P + kb + 4] };
                mma_f16(c4[ch], af, bf);
            }
        }

        // E = exp(S*SCL); stage to Ph (half2: two adjacent cols per lane)
        float eA = 0.f, eB = 0.f;
#pragma unroll
        for (int ch = 0; ch < 4; ch++) {
            float e0 = fminf(ex2(c4[ch][0] * K2E), 60000.f);
            float e1 = fminf(ex2(c4[ch][1] * K2E), 60000.f);
            float e2 = fminf(ex2(c4[ch][2] * K2E), 60000.f);
            float e3 = fminf(ex2(c4[ch][3] * K2E), 60000.f);
            eA += e0 + e1;
            eB += e2 + e3;
            int cc = wn * 16 + ch * 4 + tg;
            Ph[qr * PH_P + cc]       = h2pack(e0, e1);
            Ph[(qr + 8) * PH_P + cc] = h2pack(e2, e3);
        }
#pragma unroll
        for (int off = 1; off <= 2; off <<= 1) {
            eA += __shfl_xor_sync(0xffffffffu, eA, off);
            eB += __shfl_xor_sync(0xffffffffu, eB, off);
        }
        if (tg == 0) { psum[wn * 64 + qr] = eA; psum[wn * 64 + qr + 8] = eB; }
        __syncthreads();

        // accS += E @ V ; accT += temp @ V (fp16 k16, shared B-frags)
#pragma unroll
        for (int kk = 0; kk < 4; kk++) {
            int kb = kk * 8 + tg;
            uint32_t aE[4], aT[4];
            aE[0] = Ph[qr * PH_P + kb];
            aE[1] = Ph[(qr + 8) * PH_P + kb];
            aE[2] = Ph[qr * PH_P + kb + 4];
            aE[3] = Ph[(qr + 8) * PH_P + kb + 4];
            aT[0] = Th[qr * PH_P + kb];
            aT[1] = Th[(qr + 8) * PH_P + kb];
            aT[2] = Th[qr * PH_P + kb + 4];
            aT[3] = Th[(qr + 8) * PH_P + kb + 4];
#pragma unroll
            for (int ch = 0; ch < 8; ch++) {
                int nc = wn * 64 + ch * 8 + g;
                uint32_t bf[2] = { Vp[(kk * 8 + tg) * VP_P + nc],
                                   Vp[(kk * 8 + tg + 4) * VP_P + nc] };
                mma_f16(accS[ch], aE, bf);
                mma_f16(accT[ch], aT, bf);
            }
        }
        if (tid < 64) dacc[tid] += psum[tid] + psum[64 + tid];
    }

    __syncthreads();
    if (tid < 64) {
        float d = dacc[tid] + (float)(T_ - nkt * 64);   // pad cols: exp(0)=1 each
        inv[tid] = 1.f / d;
    }
    __syncthreads();

    const float iA = inv[qr], iB = inv[qr + 8];
    const int tA = tile0 + qr, tB = tA + 8;
#pragma unroll
    for (int ch = 0; ch < 8; ch++) {
        int cc = wn * 64 + ch * 8 + 2 * tg;
        if (tA < len)
            *(float2*)&out[(size_t)(ro + tA) * C_ + cc] =
                make_float2(accS[ch][0] * iA + accT[ch][0],
                            accS[ch][1] * iA + accT[ch][1]);
        if (tB < len)
            *(float2*)&out[(size_t)(ro + tB) * C_ + cc] =
                make_float2(accS[ch][2] * iB + accT[ch][2],
                            accS[ch][3] * iB + accT[ch][3]);
    }
}

// ---------------------------------------------------------------------------
extern "C" void kernel_launch(void* const* d_in, const int* in_sizes, int n_in,
                              void* d_out, int out_size) {
    const float* x_temp    = (const float*)d_in[0];
    const float* x_stat    = (const float*)d_in[1];
    const float* temp_attn = (const float*)d_in[2];
    // d_in[3] = mask_repeat (unused; implicit from lengths)
    const int*   lengths   = (const int*)d_in[4];
    const int*   batch_idx = (const int*)d_in[5];
    const int*   pos_idx   = (const int*)d_in[6];
    const float* W1 = (const float*)d_in[7];
    const float* b1 = (const float*)d_in[8];
    const float* g1 = (const float*)d_in[9];
    const float* be1= (const float*)d_in[10];
    const float* mu1= (const float*)d_in[11];
    const float* v1 = (const float*)d_in[12];
    const float* W2 = (const float*)d_in[13];
    const float* b2 = (const float*)d_in[14];
    const float* g2 = (const float*)d_in[15];
    const float* be2= (const float*)d_in[16];
    const float* mu2= (const float*)d_in[17];
    const float* v2 = (const float*)d_in[18];

    const int N = in_sizes[0] / 128;
    float* out = (float*)d_out;

    cudaFuncSetAttribute(k1_mma, cudaFuncAttributeMaxDynamicSharedMemorySize,
                         K1_SMEM_FLOATS * 4);
    cudaFuncSetAttribute(attn_fused, cudaFuncAttributeMaxDynamicSharedMemorySize,
                         AT_SMEM_U32 * 4);

    int nblk = (N + 63) / 64;
    k1_mma<<<nblk + 1, 256, K1_SMEM_FLOATS * 4>>>(x_temp, x_stat, batch_idx, pos_idx,
                                                  W1, b1, g1, be1, mu1, v1,
                                                  W2, b2, g2, be2, mu2, v2,
                                                  out + (size_t)N * C_, N);
    dim3 grid(T_ / 64, B_);
    attn_fused<<<grid, 256, AT_SMEM_U32 * 4>>>(lengths, temp_attn, out);
}

// round 15
// speedup vs baseline: 1.0259x; 1.0008x over previous
#include <cuda_runtime.h>
#include <cuda_fp16.h>
#include <cstdint>

#define B_   32
#define T_   1024
#define C_   128
#define EPS_ 1e-5f
#define SCL  0.08838834764831845f          // 1/sqrt(128)
#define K2E  0.1275187502506137f           // SCL * log2(e)

// Scratch (deterministic: valid slots rewritten identically each launch;
// zero-initialized padded slots never written).
__device__ float g_padded[B_ * T_ * C_];   // 16 MB

// ---------------------------------------------------------------------------
__device__ __forceinline__ float f2tf(float x) {
    uint32_t u;
    asm("cvt.rna.tf32.f32 %0, %1;" : "=r"(u) : "f"(x));
    return __uint_as_float(u);
}
__device__ __forceinline__ float ex2(float x) {
    float r;
    asm("ex2.approx.f32 %0, %1;" : "=f"(r) : "f"(x));
    return r;
}
__device__ __forceinline__ uint32_t h2pack(float a, float b) {
    __half2 h = __floats2half2_rn(a, b);
    return *(uint32_t*)&h;
}
__device__ __forceinline__ void mma_tf32(float* c, const float* a, const float* b) {
    const uint32_t* A = reinterpret_cast<const uint32_t*>(a);
    const uint32_t* Bp = reinterpret_cast<const uint32_t*>(b);
    asm volatile(
        "mma.sync.aligned.m16n8k8.row.col.f32.tf32.tf32.f32 "
        "{%0,%1,%2,%3}, {%4,%5,%6,%7}, {%8,%9}, {%0,%1,%2,%3};\n"
        : "+f"(c[0]), "+f"(c[1]), "+f"(c[2]), "+f"(c[3])
        : "r"(A[0]), "r"(A[1]), "r"(A[2]), "r"(A[3]), "r"(Bp[0]), "r"(Bp[1]));
}
__device__ __forceinline__ void mma_f16(float* c, const uint32_t* a, const uint32_t* b) {
    asm volatile(
        "mma.sync.aligned.m16n8k16.row.col.f32.f16.f16.f32 "
        "{%0,%1,%2,%3}, {%4,%5,%6,%7}, {%8,%9}, {%0,%1,%2,%3};\n"
        : "+f"(c[0]), "+f"(c[1]), "+f"(c[2]), "+f"(c[3])
        : "r"(a[0]), "r"(a[1]), "r"(a[2]), "r"(a[3]), "r"(b[0]), "r"(b[1]));
}

// ---------------------------------------------------------------------------
// K1 (tf32 MMA): h = leaky(BN(concat(x_temp, x_stat[bidx]) @ W1^T + b1))
// Last block (blockIdx.x == gridDim.x-1) instead computes the stat branch.
// ---------------------------------------------------------------------------
#define K1_SMEM_FLOATS (64 * 68 + 128 * 68)

__global__ void __launch_bounds__(256, 2)
k1_mma(const float* __restrict__ x_temp, const float* __restrict__ x_stat,
       const int* __restrict__ bidx, const int* __restrict__ pidx,
       const float* __restrict__ W1, const float* __restrict__ b1,
       const float* __restrict__ g1, const float* __restrict__ be1,
       const float* __restrict__ mu1, const float* __restrict__ v1,
       const float* __restrict__ W2, const float* __restrict__ b2,
       const float* __restrict__ g2, const float* __restrict__ be2,
       const float* __restrict__ mu2, const float* __restrict__ v2,
       float* __restrict__ stat_out, int N) {
    extern __shared__ float sm[];

    // ---- stat branch block (tiny: 32x64 GEMM + BN + leaky) ----
    if (blockIdx.x == gridDim.x - 1) {
        const int tid = threadIdx.x;
        int c = tid & 63;
        int b0r = tid >> 6;            // 0..3
        float s = g2[c] * rsqrtf(v2[c] + EPS_);
        float o = (b2[c] - mu2[c]) * s + be2[c];
#pragma unroll
        for (int bb = 0; bb < 8; bb++) {
            int b = b0r * 8 + bb;
            float a = 0.f;
#pragma unroll 8
            for (int k = 0; k < 64; k++) a += x_stat[b * 64 + k] * W2[c * 64 + k];
            float h = a * s + o;
            stat_out[b * 64 + c] = (h >= 0.f) ? h : 0.01f * h;
        }
        return;
    }

    float* Xs = sm;              // [64][68]
    float* Ws = sm + 64 * 68;    // [128][68]

    const int n0  = blockIdx.x * 64;
    const int tid = threadIdx.x;
    const int wid = tid >> 5, lane = tid & 31;
    const int wm  = wid >> 1, wn = wid & 1;
    const int g   = lane >> 2, tg = lane & 3;
    const int qr  = wm * 16 + g;

    float acc[8][4];
#pragma unroll
    for (int ch = 0; ch < 8; ch++)
#pragma unroll
        for (int i = 0; i < 4; i++) acc[ch][i] = 0.f;

    for (int ck = 0; ck < 3; ck++) {
        __syncthreads();
#pragma unroll
        for (int it = 0; it < 4; it++) {
            int e = (tid + it * 256) * 4;
            int r = e >> 6, k4 = e & 63;
            int n = n0 + r;
            float4 v = make_float4(0.f, 0.f, 0.f, 0.f);
            if (n < N) {
                if (ck < 2)
                    v = *(const float4*)&x_temp[(size_t)n * 128 + ck * 64 + k4];
                else
                    v = *(const float4*)&x_stat[bidx[n] * 64 + k4];
            }
            *(float4*)&Xs[r * 68 + k4] =
                make_float4(f2tf(v.x), f2tf(v.y), f2tf(v.z), f2tf(v.w));
        }
#pragma unroll
        for (int it = 0; it < 8; it++) {
            int e = (tid + it * 256) * 4;
            int c = e >> 6, k4 = e & 63;
            float4 v = *(const float4*)&W1[(size_t)c * 192 + ck * 64 + k4];
            *(float4*)&Ws[c * 68 + k4] =
                make_float4(f2tf(v.x), f2tf(v.y), f2tf(v.z), f2tf(v.w));
        }
        __syncthreads();

#pragma unroll
        for (int kk = 0; kk < 8; kk++) {
            int kb = kk * 8 + tg;
            float af[4];
            af[0] = Xs[qr * 68 + kb];
            af[1] = Xs[(qr + 8) * 68 + kb];
            af[2] = Xs[qr * 68 + kb + 4];
            af[3] = Xs[(qr + 8) * 68 + kb + 4];
#pragma unroll
            for (int ch = 0; ch < 8; ch++) {
                int nc = wn * 64 + ch * 8 + g;
                float bb[2] = { Ws[nc * 68 + kb], Ws[nc * 68 + kb + 4] };
                mma_tf32(acc[ch], af, bb);
            }
        }
    }

    int nA = n0 + qr, nB = n0 + qr + 8;
    int bbA = 0, ttA = 0, bbB = 0, ttB = 0;
    if (nA < N) { bbA = bidx[nA]; ttA = pidx[nA]; }
    if (nB < N) { bbB = bidx[nB]; ttB = pidx[nB]; }
#pragma unroll
    for (int ch = 0; ch < 8; ch++) {
        int c = wn * 64 + ch * 8 + 2 * tg;
        float s0 = g1[c]     * rsqrtf(v1[c]     + EPS_);
        float s1 = g1[c + 1] * rsqrtf(v1[c + 1] + EPS_);
        float o0 = (b1[c]     - mu1[c])     * s0 + be1[c];
        float o1 = (b1[c + 1] - mu1[c + 1]) * s1 + be1[c + 1];
        if (nA < N) {
            float h0 = acc[ch][0] * s0 + o0;
            float h1 = acc[ch][1] * s1 + o1;
            h0 = (h0 >= 0.f) ? h0 : 0.01f * h0;
            h1 = (h1 >= 0.f) ? h1 : 0.01f * h1;
            *(float2*)&g_padded[((size_t)bbA * T_ + ttA) * C_ + c] = make_float2(h0, h1);
        }
        if (nB < N) {
            float h2 = acc[ch][2] * s0 + o0;
            float h3 = acc[ch][3] * s1 + o1;
            h2 = (h2 >= 0.f) ? h2 : 0.01f * h2;
            h3 = (h3 >= 0.f) ? h3 : 0.01f * h3;
            *(float2*)&g_padded[((size_t)bbB * T_ + ttB) * C_ + c] = make_float2(h2, h3);
        }
    }
}

// ---------------------------------------------------------------------------
// Fused attention, fp16 m16n8k16 MMA (fp32 accum):
//   per key tile: S = QK^T, E = exp(S*SCL) (no max-sub: logits bounded),
//   d += rowsum(E), accS += E@V, accT += temp@V;  out = accS/(d+pad) + accT
// smem (b32 units):
//   Qh [64][68]  row-major half2   (QK A-frags CF: bank 4g+tg)
//   Kh [64][68]  row-major half2   (QK B-frags CF)
//   Vp [32][136] key-paired half2: Vp[k2][ch] = (V[2k2][ch], V[2k2+1][ch])
//                                  (PV B-frags = 1 LDS.32, CF: bank 8tg+g)
//   Ph/Th [64][36] half2           (PV A-frags CF)
// ---------------------------------------------------------------------------
#define QH_P 68
#define KH_P 68
#define VP_P 136
#define PH_P 36
#define AT_SMEM_U32 (64*QH_P + 64*KH_P + 32*VP_P + 64*PH_P + 64*PH_P + 64 + 128)

__global__ void __launch_bounds__(256, 2)
attn_fused(const int* __restrict__ lengths,
           const float* __restrict__ temp_attn,
           float* __restrict__ out) {
    extern __shared__ uint32_t smu[];
    uint32_t* Qh = smu;                      // [64][68]
    uint32_t* Kh = Qh + 64 * QH_P;           // [64][68]
    uint32_t* Vp = Kh + 64 * KH_P;           // [32][136]
    uint32_t* Ph = Vp + 32 * VP_P;           // [64][36]
    uint32_t* Th = Ph + 64 * PH_P;           // [64][36]
    float*   dacc = (float*)(Th + 64 * PH_P);  // [64]
    float*   psum = dacc + 64;                 // [2][64]
    float*   inv  = psum;                      // reused in epilogue

    const int b = blockIdx.y;
    const int len = lengths[b];
    const int tile0 = blockIdx.x * 64;
    if (tile0 >= len) return;

    const int tid  = threadIdx.x;
    const int wid  = tid >> 5, lane = tid & 31;
    const int wm   = wid >> 1, wn = wid & 1;
    const int g    = lane >> 2, tg = lane & 3;
    const int qr   = wm * 16 + g;
    const float* pb = g_padded + (size_t)b * T_ * C_;

    int ro = 0;
    for (int i = 0; i < b; i++) ro += lengths[i];

    if (tid < 64) dacc[tid] = 0.f;

    // Q tile: row pairs -> half2 rows
#pragma unroll
    for (int it = 0; it < 4; it++) {
        int idx = tid + it * 256;            // 0..1023
        int r2 = idx >> 5, cb = (idx & 31) * 4;
        float4 v0 = *(const float4*)&pb[(size_t)(tile0 + 2 * r2)     * C_ + cb];
        float4 v1 = *(const float4*)&pb[(size_t)(tile0 + 2 * r2 + 1) * C_ + cb];
        *(uint2*)&Qh[(2 * r2)     * QH_P + cb / 2] =
            make_uint2(h2pack(v0.x, v0.y), h2pack(v0.z, v0.w));
        *(uint2*)&Qh[(2 * r2 + 1) * QH_P + cb / 2] =
            make_uint2(h2pack(v1.x, v1.y), h2pack(v1.z, v1.w));
    }

    float accS[8][4], accT[8][4];
#pragma unroll
    for (int ch = 0; ch < 8; ch++)
#pragma unroll
        for (int i = 0; i < 4; i++) { accS[ch][i] = 0.f; accT[ch][i] = 0.f; }

    const float* tb = temp_attn + ((size_t)b * T_ + tile0) * T_;
    const int nkt = (len + 63) >> 6;

    for (int kt = 0; kt < nkt; kt++) {
        __syncthreads();
        // K/V tile: read row pairs; Kh row-major + Vp key-paired transpose
#pragma unroll
        for (int it = 0; it < 4; it++) {
            int idx = tid + it * 256;
            int r2 = idx >> 5, cb = (idx & 31) * 4;
            const float* src = &pb[(size_t)(kt * 64 + 2 * r2) * C_ + cb];
            float4 v0 = *(const float4*)src;
            float4 v1 = *(const float4*)(src + C_);
            *(uint2*)&Kh[(2 * r2)     * KH_P + cb / 2] =
                make_uint2(h2pack(v0.x, v0.y), h2pack(v0.z, v0.w));
            *(uint2*)&Kh[(2 * r2 + 1) * KH_P + cb / 2] =
                make_uint2(h2pack(v1.x, v1.y), h2pack(v1.z, v1.w));
            Vp[r2 * VP_P + cb]     = h2pack(v0.x, v1.x);
            Vp[r2 * VP_P + cb + 1] = h2pack(v0.y, v1.y);
            Vp[r2 * VP_P + cb + 2] = h2pack(v0.z, v1.z);
            Vp[r2 * VP_P + cb + 3] = h2pack(v0.w, v1.w);
        }
        // temp tile -> half2
#pragma unroll
        for (int it = 0; it < 4; it++) {
            int e = (tid + it * 256) * 4;
            int r = e >> 6, c = e & 63;
            float4 v = *(const float4*)&tb[(size_t)r * T_ + kt * 64 + c];
            *(uint2*)&Th[r * PH_P + c / 2] =
                make_uint2(h2pack(v.x, v.y), h2pack(v.z, v.w));
        }
        __syncthreads();

        // S = Q K^T (warp: 16 rows x 32 keys), fp16 k16
        float c4[4][4];
#pragma unroll
        for (int ch = 0; ch < 4; ch++)
#pragma unroll
            for (int i = 0; i < 4; i++) c4[ch][i] = 0.f;
#pragma unroll
        for (int kk = 0; kk < 8; kk++) {
            int kb = kk * 8 + tg;
            uint32_t af[4];
            af[0] = Qh[qr * QH_P + kb];
            af[1] = Qh[(qr + 8) * QH_P + kb];
            af[2] = Qh[qr * QH_P + kb + 4];
            af[3] = Qh[(qr + 8) * QH_P + kb + 4];
#pragma unroll
            for (int ch = 0; ch < 4; ch++) {
                int nc = wn * 32 + ch * 8 + g;
                uint32_t bf[2] = { Kh[nc * KH_P + kb], Kh[nc * KH_P + kb + 4] };
                mma_f16(c4[ch], af, bf);
            }
        }

        // E = exp(S*SCL); stage to Ph (half2: two adjacent cols per lane)
        float eA = 0.f, eB = 0.f;
#pragma unroll
        for (int ch = 0; ch < 4; ch++) {
            float e0 = fminf(ex2(c4[ch][0] * K2E), 60000.f);
            float e1 = fminf(ex2(c4[ch][1] * K2E), 60000.f);
            float e2 = fminf(ex2(c4[ch][2] * K2E), 60000.f);
            float e3 = fminf(ex2(c4[ch][3] * K2E), 60000.f);
            eA += e0 + e1;
            eB += e2 + e3;
            int cc = wn * 16 + ch * 4 + tg;
            Ph[qr * PH_P + cc]       = h2pack(e0, e1);
            Ph[(qr + 8) * PH_P + cc] = h2pack(e2, e3);
        }
#pragma unroll
        for (int off = 1; off <= 2; off <<= 1) {
            eA += __shfl_xor_sync(0xffffffffu, eA, off);
            eB += __shfl_xor_sync(0xffffffffu, eB, off);
        }
        if (tg == 0) { psum[wn * 64 + qr] = eA; psum[wn * 64 + qr + 8] = eB; }
        __syncthreads();

        // accS += E @ V ; accT += temp @ V (fp16 k16, shared B-frags)
#pragma unroll
        for (int kk = 0; kk < 4; kk++) {
            int kb = kk * 8 + tg;
            uint32_t aE[4], aT[4];
            aE[0] = Ph[qr * PH_P + kb];
            aE[1] = Ph[(qr + 8) * PH_P + kb];
            aE[2] = Ph[qr * PH_P + kb + 4];
            aE[3] = Ph[(qr + 8) * PH_P + kb + 4];
            aT[0] = Th[qr * PH_P + kb];
            aT[1] = Th[(qr + 8) * PH_P + kb];
            aT[2] = Th[qr * PH_P + kb + 4];
            aT[3] = Th[(qr + 8) * PH_P + kb + 4];
#pragma unroll
            for (int ch = 0; ch < 8; ch++) {
                int nc = wn * 64 + ch * 8 + g;
                uint32_t bf[2] = { Vp[(kk * 8 + tg) * VP_P + nc],
                                   Vp[(kk * 8 + tg + 4) * VP_P + nc] };
                mma_f16(accS[ch], aE, bf);
                mma_f16(accT[ch], aT, bf);
            }
        }
        if (tid < 64) dacc[tid] += psum[tid] + psum[64 + tid];
    }

    __syncthreads();
    if (tid < 64) {
        float d = dacc[tid] + (float)(T_ - nkt * 64);   // pad cols: exp(0)=1 each
        inv[tid] = 1.f / d;
    }
    __syncthreads();

    const float iA = inv[qr], iB = inv[qr + 8];
    const int tA = tile0 + qr, tB = tA + 8;
#pragma unroll
    for (int ch = 0; ch < 8; ch++) {
        int cc = wn * 64 + ch * 8 + 2 * tg;
        if (tA < len)
            *(float2*)&out[(size_t)(ro + tA) * C_ + cc] =
                make_float2(accS[ch][0] * iA + accT[ch][0],
                            accS[ch][1] * iA + accT[ch][1]);
        if (tB < len)
            *(float2*)&out[(size_t)(ro + tB) * C_ + cc] =
                make_float2(accS[ch][2] * iB + accT[ch][2],
                            accS[ch][3] * iB + accT[ch][3]);
    }
}

// ---------------------------------------------------------------------------
extern "C" void kernel_launch(void* const* d_in, const int* in_sizes, int n_in,
                              void* d_out, int out_size) {
    const float* x_temp    = (const float*)d_in[0];
    const float* x_stat    = (const float*)d_in[1];
    const float* temp_attn = (const float*)d_in[2];
    // d_in[3] = mask_repeat (unused; implicit from lengths)
    const int*   lengths   = (const int*)d_in[4];
    const int*   batch_idx = (const int*)d_in[5];
    const int*   pos_idx   = (const int*)d_in[6];
    const float* W1 = (const float*)d_in[7];
    const float* b1 = (const float*)d_in[8];
    const float* g1 = (const float*)d_in[9];
    const float* be1= (const float*)d_in[10];
    const float* mu1= (const float*)d_in[11];
    const float* v1 = (const float*)d_in[12];
    const float* W2 = (const float*)d_in[13];
    const float* b2 = (const float*)d_in[14];
    const float* g2 = (const float*)d_in[15];
    const float* be2= (const float*)d_in[16];
    const float* mu2= (const float*)d_in[17];
    const float* v2 = (const float*)d_in[18];

    const int N = in_sizes[0] / 128;
    float* out = (float*)d_out;

    cudaFuncSetAttribute(k1_mma, cudaFuncAttributeMaxDynamicSharedMemorySize,
                         K1_SMEM_FLOATS * 4);
    cudaFuncSetAttribute(attn_fused, cudaFuncAttributeMaxDynamicSharedMemorySize,
                         AT_SMEM_U32 * 4);

    int nblk = (N + 63) / 64;
    k1_mma<<<nblk + 1, 256, K1_SMEM_FLOATS * 4>>>(x_temp, x_stat, batch_idx, pos_idx,
                                                  W1, b1, g1, be1, mu1, v1,
                                                  W2, b2, g2, be2, mu2, v2,
                                                  out + (size_t)N * C_, N);
    dim3 grid(T_ / 64, B_);
    attn_fused<<<grid, 256, AT_SMEM_U32 * 4>>>(lengths, temp_attn, out);
}